// round 13
// baseline (speedup 1.0000x reference)
#include <cuda_runtime.h>
#include <cuda_bf16.h>
#include <cuda_fp16.h>
#include <cstdint>
#include <cstddef>

#define B_ 2
#define C_ 256
#define H_ 128
#define W_ 128
#define Q_ 32768
#define HP 130
#define HW_ (H_*W_)

// ---------------- static device scratch ----------------
__device__ __align__(16) __half g_Ah[(size_t)B_*HP*HP*C_];   // padded NHWC hi (fp16)
__device__ __align__(16) __half g_Al[(size_t)B_*HP*HP*C_];   // padded NHWC lo (fp16)
__device__ __align__(16) __half g_Wth[512*2304];             // conv W^T [oc][k] hi
__device__ __align__(16) __half g_Wtl[512*2304];             // lo
__device__ __align__(16) __half g_Mh[3*256*256];             // mlp W^T [l][n][k] fp16
__device__ float g_cbias[512];
__device__ __align__(16) float g_cf[(size_t)B_*HW_*512];     // conv out [b][pix][512] fp32
__device__ int g_next;                                       // work-queue cursor
__device__ int g_done[2];                                    // conv blocks completed per batch

// ---------------- helpers ----------------
__device__ __forceinline__ uint32_t smem_u32(const void* p){
    return (uint32_t)__cvta_generic_to_shared(p);
}
__device__ __forceinline__ void ldsm4(uint32_t& r0,uint32_t& r1,uint32_t& r2,uint32_t& r3,uint32_t a){
    asm volatile("ldmatrix.sync.aligned.m8n8.x4.shared.b16 {%0,%1,%2,%3},[%4];"
        :"=r"(r0),"=r"(r1),"=r"(r2),"=r"(r3):"r"(a));
}
__device__ __forceinline__ void cp16(uint32_t d, const void* s){
    asm volatile("cp.async.ca.shared.global [%0],[%1],16;"::"r"(d),"l"(s));
}
__device__ __forceinline__ void cp_commit(){ asm volatile("cp.async.commit_group;"); }
__device__ __forceinline__ void mma16816h(float* c, const uint32_t* a, const uint32_t* b){
    asm volatile("mma.sync.aligned.m16n8k16.row.col.f32.f16.f16.f32 "
        "{%0,%1,%2,%3},{%4,%5,%6,%7},{%8,%9},{%0,%1,%2,%3};"
        : "+f"(c[0]),"+f"(c[1]),"+f"(c[2]),"+f"(c[3])
        : "r"(a[0]),"r"(a[1]),"r"(a[2]),"r"(a[3]),"r"(b[0]),"r"(b[1]));
}
__device__ __forceinline__ uint32_t pack_hi16(float2 v){
    __half2 h = __floats2half2_rn(v.x, v.y);
    return *reinterpret_cast<uint32_t*>(&h);
}
// fast sin/cos of pi*x (abs err < 4e-6)
__device__ __forceinline__ void sincospif_fast(float x, float* sp, float* cp){
    float n = rintf(x);
    float r = x - n;
    float r2 = r*r;
    float s = fmaf(r2, 0.08214588661f, -0.5992645293f);
    s = fmaf(r2, s, 2.550164040f);
    s = fmaf(r2, s, -5.167712780f);
    s = fmaf(r2, s, 3.14159265359f);
    s *= r;
    float c = fmaf(r2, -0.02580689139f, 0.2353306304f);
    c = fmaf(r2, c, -1.335262769f);
    c = fmaf(r2, c, 4.058712126f);
    c = fmaf(r2, c, -4.934802201f);
    c = fmaf(r2, c, 1.0f);
    uint32_t sg = ((uint32_t)(int)n) << 31;
    *sp = __uint_as_float(__float_as_uint(s) ^ sg);
    *cp = __uint_as_float(__float_as_uint(c) ^ sg);
}

// ---------------- prep kernels ----------------
__global__ void prep_feat(const float* __restrict__ feat){
    __shared__ float tile[32][33];
    const int bx = blockIdx.x;
    const int cg = bx >> 2, xg = bx & 3;
    const int y = blockIdx.y, b = blockIdx.z;
    const int tx = threadIdx.x, ty = threadIdx.y;
    #pragma unroll
    for (int k = 0; k < 4; ++k){
        int c = cg*32 + ty + k*8;
        int x = xg*32 + tx;
        tile[ty + k*8][tx] = feat[(((size_t)(b*C_ + c))*H_ + y)*W_ + x];
    }
    __syncthreads();
    #pragma unroll
    for (int k = 0; k < 4; ++k){
        int c = cg*32 + tx;
        int x = xg*32 + ty + k*8;
        float v = tile[tx][ty + k*8];
        __half h = __float2half_rn(v);
        size_t o = ((size_t)((b*HP + y + 1)*HP + x + 1))*C_ + c;
        g_Ah[o] = h;
        g_Al[o] = __float2half_rn(v - __half2float(h));
    }
}

__global__ void border_zero(){
    int id = blockIdx.x*256 + threadIdx.x;
    if (id >= B_*HP*HP) return;
    int xx = id % HP, rest = id / HP;
    int yy = rest % HP;
    if (yy >= 1 && yy <= H_ && xx >= 1 && xx <= W_) return;
    uint4 z = make_uint4(0,0,0,0);
    uint4* ph = (uint4*)(g_Ah + (size_t)id*C_);
    uint4* pl = (uint4*)(g_Al + (size_t)id*C_);
    #pragma unroll
    for (int i = 0; i < 32; ++i){ ph[i] = z; pl[i] = z; }
}

__global__ void prep_wconv(const float* __restrict__ cw, const float* __restrict__ cb,
                           const float* __restrict__ fw, const float* __restrict__ fb){
    int id = blockIdx.x*256 + threadIdx.x;
    if (id < 512) g_cbias[id] = (id < 256) ? cb[id] : fb[id-256];
    if (id >= 512*2304) return;
    int oc = id / 2304, k = id % 2304;
    int tap = k >> 8, ic = k & 255;
    float v = (oc < 256) ? cw[(oc*256 + ic)*9 + tap]
                         : fw[((oc-256)*256 + ic)*9 + tap];
    __half h = __float2half_rn(v);
    g_Wth[id] = h;
    g_Wtl[id] = __float2half_rn(v - __half2float(h));
}

__global__ void prep_wmlp(const float* __restrict__ w0, const float* __restrict__ w1,
                          const float* __restrict__ w2){
    int id = blockIdx.x*256 + threadIdx.x;
    if (blockIdx.x == 0 && threadIdx.x == 0){
        g_next = 0; g_done[0] = 0; g_done[1] = 0;   // reset work queue every launch
    }
    if (id >= 3*65536) return;
    int l = id >> 16, r = id & 65535;
    int n = r >> 8, k = r & 255;
    const float* w = (l==0) ? w0 : (l==1) ? w1 : w2;
    g_Mh[id] = __float2half_rn(w[k*256 + n]);
}

// ---------------- fused persistent kernel ----------------
// work items: [0,512)   conv: b = i>>8, r = i&255, freq (3-term) if r<128, y = r&127
//             [512,2560) point: p = i-512, batch = p>>10, g0 = p*32
#define ST_AH 0
#define ST_AL 5120
#define ST_BH 10240
#define ST_BL 20480
#define ST_SZ 30720                 // halves per conv stage (61440 B); 3 stages = 184320 B
#define MROWS 128
#define NPTS  32
#define XP    264
#define WP2   72
#define WSTG2 (256*WP2)
#define N_ITEMS 2560

__global__ __launch_bounds__(512) void fused_kernel(
        const float* __restrict__ pc,
        const float* __restrict__ phase_w,
        const float* __restrict__ b0, const float* __restrict__ b1,
        const float* __restrict__ b2,
        const float* __restrict__ w3, const float* __restrict__ b3,
        const float* __restrict__ coarse,
        float* __restrict__ out) {
    extern __shared__ __align__(16) char smb[];
    __shared__ int s_item;
    const int t = threadIdx.x, warp = t>>5, lane = t&31;
    const int rsel = lane & 15, kgrp = (lane >> 4)*8;
    const int m0c = (warp>>2)*32, n0c = (warp&3)*64;   // shared warp tiling (conv & point)

    for (;;){
        if (t == 0) s_item = atomicAdd(&g_next, 1);
        __syncthreads();
        const int item = s_item;
        if (item >= N_ITEMS) break;

        if (item < 512){
            // ================= CONV ITEM =================
            const int b = item >> 8, r = item & 255;
            const bool three = (r < 128);
            const int y = r & 127;
            const int oc0 = three ? 256 : 0;
            __half* cs = (__half*)smb;

            float acc[2][8][4];
            #pragma unroll
            for (int i=0;i<2;++i)
                #pragma unroll
                for (int j=0;j<8;++j)
                    #pragma unroll
                    for (int q=0;q<4;++q) acc[i][j][q] = 0.f;

            auto issue = [&](int s, int buf){
                const int tap = s >> 3, sub = s & 7;
                const int ky = tap/3, kx = tap - ky*3;
                const int k0 = tap*256 + sub*32;
                __half* dstb = cs + buf*ST_SZ;
                {   // A hi: 128 rows x 4 chunks = 512 ops
                    int row = t >> 2, ch = t & 3;
                    cp16(smem_u32(dstb + ST_AH + row*40 + ch*8),
                         g_Ah + ((size_t)((b*HP + y+ky)*HP + row + kx))*C_ + sub*32 + ch*8);
                    if (three)
                        cp16(smem_u32(dstb + ST_AL + row*40 + ch*8),
                             g_Al + ((size_t)((b*HP + y+ky)*HP + row + kx))*C_ + sub*32 + ch*8);
                }
                #pragma unroll
                for (int j=0;j<2;++j){  // B hi: 256 rows x 4 chunks = 1024 ops
                    int id = t + j*512;
                    int row = id >> 2, ch = id & 3;
                    cp16(smem_u32(dstb + ST_BH + row*40 + ch*8),
                         g_Wth + (size_t)(oc0 + row)*2304 + k0 + ch*8);
                    if (three)
                        cp16(smem_u32(dstb + ST_BL + row*40 + ch*8),
                             g_Wtl + (size_t)(oc0 + row)*2304 + k0 + ch*8);
                }
                cp_commit();
            };

            issue(0, 0); issue(1, 1);
            asm volatile("cp.async.wait_group 1;");
            __syncthreads();

            for (int s = 0; s < 72; ++s){
                const int buf = s % 3;
                if (s + 2 < 72) issue(s + 2, (s + 2) % 3);
                const __half* Ah = cs + buf*ST_SZ + ST_AH;
                const __half* Al = cs + buf*ST_SZ + ST_AL;
                const __half* Bh = cs + buf*ST_SZ + ST_BH;
                const __half* Bl = cs + buf*ST_SZ + ST_BL;
                #pragma unroll
                for (int k16 = 0; k16 < 32; k16 += 16){
                    uint32_t ah[2][4], al[2][4];
                    #pragma unroll
                    for (int mi=0;mi<2;++mi){
                        ldsm4(ah[mi][0],ah[mi][1],ah[mi][2],ah[mi][3],
                              smem_u32(Ah + (m0c+mi*16+rsel)*40 + k16 + kgrp));
                        if (three)
                            ldsm4(al[mi][0],al[mi][1],al[mi][2],al[mi][3],
                                  smem_u32(Al + (m0c+mi*16+rsel)*40 + k16 + kgrp));
                    }
                    #pragma unroll
                    for (int nj=0;nj<4;++nj){
                        uint32_t r0,r1,r2,r3;
                        ldsm4(r0,r1,r2,r3, smem_u32(Bh + (n0c+nj*16+rsel)*40 + k16 + kgrp));
                        uint32_t bh0[2] = {r0, r2}, bh1[2] = {r1, r3};
                        if (three){
                            uint32_t q0,q1,q2,q3;
                            ldsm4(q0,q1,q2,q3, smem_u32(Bl + (n0c+nj*16+rsel)*40 + k16 + kgrp));
                            uint32_t bl0[2] = {q0, q2}, bl1[2] = {q1, q3};
                            #pragma unroll
                            for (int mi=0;mi<2;++mi){
                                mma16816h(acc[mi][2*nj],   ah[mi], bh0);
                                mma16816h(acc[mi][2*nj],   al[mi], bh0);
                                mma16816h(acc[mi][2*nj],   ah[mi], bl0);
                                mma16816h(acc[mi][2*nj+1], ah[mi], bh1);
                                mma16816h(acc[mi][2*nj+1], al[mi], bh1);
                                mma16816h(acc[mi][2*nj+1], ah[mi], bl1);
                            }
                        } else {
                            #pragma unroll
                            for (int mi=0;mi<2;++mi){
                                mma16816h(acc[mi][2*nj],   ah[mi], bh0);
                                mma16816h(acc[mi][2*nj+1], ah[mi], bh1);
                            }
                        }
                    }
                }
                if (s < 71){
                    if (s + 2 < 72) asm volatile("cp.async.wait_group 1;");
                    else            asm volatile("cp.async.wait_group 0;");
                    __syncthreads();
                }
            }

            #pragma unroll
            for (int mi=0;mi<2;++mi){
                const int x = m0c + mi*16 + (lane>>2);
                #pragma unroll
                for (int ni=0;ni<8;++ni){
                    const int col = oc0 + n0c + ni*8 + (lane&3)*2;
                    float2 bb = *(const float2*)&g_cbias[col];
                    float* o0 = g_cf + ((size_t)(b*HW_ + y*W_ + x))*512 + col;
                    float* o1 = g_cf + ((size_t)(b*HW_ + y*W_ + x + 8))*512 + col;
                    *(float2*)o0 = make_float2(acc[mi][ni][0]+bb.x, acc[mi][ni][1]+bb.y);
                    *(float2*)o1 = make_float2(acc[mi][ni][2]+bb.x, acc[mi][ni][3]+bb.y);
                }
            }
            __threadfence();
            __syncthreads();
            if (t == 0) atomicAdd(&g_done[b], 1);
            __syncthreads();
        } else {
            // ================= POINT ITEM =================
            const int p = item - 512;
            const int pb = p >> 10;
            // wait for conv of this batch
            if (t == 0){
                int v;
                for (;;){
                    asm volatile("ld.global.acquire.gpu.b32 %0,[%1];"
                                 : "=r"(v) : "l"(&g_done[pb]) : "memory");
                    if (v >= 256) break;
                    __nanosleep(200);
                }
            }
            __syncthreads();
            __threadfence();

            __half* Xh = (__half*)smb;                 // 128*264
            __half* Wt = Xh + MROWS*XP;                // 2 stages * WSTG2
            float* fm = (float*)(Wt + 2*WSTG2);
            float* ph     = fm;                    // 256
            float* s_rel0 = ph + 256;              // 128
            float* s_rel1 = s_rel0 + 128;          // 128
            float* s_area = s_rel1 + 128;          // 128
            int*   s_pix  = (int*)(s_area + 128);  // 128
            int*   s_phof = s_pix + 128;           // 128
            float* w3s    = (float*)(s_phof + 128);// 514
            float* s_pr   = w3s + 514;             // 256
            const int g0 = p * NPTS;

            if (t < 128) {
                float p0 = phase_w[2*t], p1 = phase_w[2*t+1];
                ph[t]       = fmaf(8.f,   p0, 8.f*p1);
                ph[128 + t] = fmaf(128.f, p0, 128.f*p1);
            }
            for (int i = t; i < 514; i += 512)
                w3s[i] = (i < 512) ? w3[i] : b3[i - 512];

            if (t < MROWS) {
                const int p_local = t >> 2, s = t & 3;
                const int g = g0 + p_local;
                const int q = g & (Q_ - 1);
                const float pc0 = pc[2*g], pc1 = pc[2*g + 1];
                const float SH_P = (float)( 1.0/128.0 + 1e-6);
                const float SH_M = (float)(-1.0/128.0 + 1e-6);
                const float LO = (float)(-1.0 + 1e-6), HI = (float)(1.0 - 1e-6);
                float cy = pc0 + ((s >= 2) ? SH_P : SH_M);
                float cx = pc1 + ((s & 1) ? SH_P : SH_M);
                cy = fminf(fmaxf(cy, LO), HI);
                cx = fminf(fmaxf(cx, LO), HI);
                int iy = (int)rintf(((cy + 1.f)*128.f - 1.f)*0.5f);
                int ix = (int)rintf(((cx + 1.f)*128.f - 1.f)*0.5f);
                iy = min(max(iy, 0), 127); ix = min(max(ix, 0), 127);
                float qcy = -0.9921875f + 0.015625f*(float)iy;
                float qcx = -0.9921875f + 0.015625f*(float)ix;
                float rel0 = (pc0 - qcy)*128.f;
                float rel1 = (pc1 - qcx)*128.f;
                s_pix[t]  = iy*W_ + ix;
                s_rel0[t] = rel0;  s_rel1[t] = rel1;
                s_area[t] = fabsf(rel0*rel1) + 1e-9f;
                s_phof[t] = (q < 2) ? 0 : 128;
            }
            __syncthreads();

            auto wissue = [&](int g, int stg){
                const int L = g >> 2, kc = g & 3;
                __half* dstb = Wt + stg*WSTG2;
                const __half* srcb = g_Mh + L*65536 + kc*64;
                #pragma unroll
                for (int j=0;j<4;++j){
                    int cid = t + j*512;
                    int row = cid >> 3, ch = cid & 7;
                    cp16(smem_u32(dstb + row*WP2 + ch*8), srcb + row*256 + ch*8);
                }
                cp_commit();
            };
            wissue(0, 0);

            {   // gather + sinusoid -> Xh
                #pragma unroll 1
                for (int rr = 0; rr < 8; ++rr) {
                    const int rI = warp*8 + rr;
                    const int g = g0 + (rI >> 2);
                    const int bb2 = g >> 15;
                    const float* base = g_cf + ((size_t)(bb2*HW_ + s_pix[rI])) * 512;
                    const float rel0 = s_rel0[rI], rel1 = s_rel1[rI];
                    const float* php = ph + s_phof[rI];
                    #pragma unroll
                    for (int i = 0; i < 2; ++i) {
                        const int kp = lane + 32*i;
                        const int k0 = 2*kp;
                        float4 f4 = *(const float4*)(base + 256 + 2*k0);
                        float2 cc = *(const float2*)(base + k0);
                        float2 cs2 = *(const float2*)(base + 128 + k0);
                        float2 ph2 = *(const float2*)(php + k0);
                        float qf0 = fmaf(f4.x, rel0, fmaf(f4.y, rel1, ph2.x));
                        float qf1 = fmaf(f4.z, rel0, fmaf(f4.w, rel1, ph2.y));
                        float sv0, cv0, sv1, cv1;
                        sincospif_fast(qf0, &sv0, &cv0);
                        sincospif_fast(qf1, &sv1, &cv1);
                        *(uint32_t*)&Xh[rI*XP + k0]       = pack_hi16(make_float2(cc.x*cv0,  cc.y*cv1));
                        *(uint32_t*)&Xh[rI*XP + 128 + k0] = pack_hi16(make_float2(cs2.x*sv0, cs2.y*sv1));
                    }
                }
            }
            asm volatile("cp.async.wait_group 0;");
            __syncthreads();

            float acc[2][8][4];
            for (int g = 0; g < 12; ++g){
                const int L = g >> 2, kc = g & 3, stg = g & 1;
                if (kc == 0){
                    #pragma unroll
                    for (int i=0;i<2;++i)
                        #pragma unroll
                        for (int j=0;j<8;++j)
                            #pragma unroll
                            for (int q=0;q<4;++q) acc[i][j][q] = 0.f;
                }
                if (g+1 < 12) wissue(g+1, (g+1)&1);

                const __half* WH = Wt + stg*WSTG2;
                #pragma unroll
                for (int kh = 0; kh < 4; ++kh){
                    const int k16 = kc*64 + kh*16;
                    uint32_t AH[2][4];
                    #pragma unroll
                    for (int mi=0;mi<2;++mi){
                        ldsm4(AH[mi][0],AH[mi][1],AH[mi][2],AH[mi][3],
                              smem_u32(Xh + (m0c+mi*16+rsel)*XP + k16 + kgrp));
                    }
                    #pragma unroll
                    for (int nj=0;nj<4;++nj){
                        uint32_t r0,r1,r2,r3;
                        ldsm4(r0,r1,r2,r3, smem_u32(WH + (n0c+nj*16+rsel)*WP2 + kh*16 + kgrp));
                        uint32_t b0r[2] = {r0, r2}, b1r[2] = {r1, r3};
                        #pragma unroll
                        for (int mi=0;mi<2;++mi){
                            mma16816h(acc[mi][2*nj],   AH[mi], b0r);
                            mma16816h(acc[mi][2*nj+1], AH[mi], b1r);
                        }
                    }
                }

                if (kc == 3){
                    __syncthreads();
                    const float* bg = (L==0) ? b0 : (L==1) ? b1 : b2;
                    #pragma unroll
                    for (int mi=0;mi<2;++mi){
                        const int rI = m0c + mi*16 + (lane>>2);
                        #pragma unroll
                        for (int ni=0;ni<8;++ni){
                            const int c = n0c + ni*8 + (lane&3)*2;
                            float2 bb = *(const float2*)&bg[c];
                            *(uint32_t*)&Xh[rI*XP + c] =
                                pack_hi16(make_float2(fmaxf(acc[mi][ni][0]+bb.x, 0.f),
                                                      fmaxf(acc[mi][ni][1]+bb.y, 0.f)));
                            *(uint32_t*)&Xh[(rI+8)*XP + c] =
                                pack_hi16(make_float2(fmaxf(acc[mi][ni][2]+bb.x, 0.f),
                                                      fmaxf(acc[mi][ni][3]+bb.y, 0.f)));
                        }
                    }
                }
                asm volatile("cp.async.wait_group 0;");
                __syncthreads();
            }

            if (t < 2*MROWS) {
                const int rI = t >> 1, c = t & 1;
                const __half* rh = Xh + rI*XP;
                float sum = w3s[512 + c];
                #pragma unroll 4
                for (int i = 0; i < 128; ++i) {
                    uint32_t hu = *(const uint32_t*)&rh[2*i];
                    __half2 hb = *reinterpret_cast<__half2*>(&hu);
                    sum = fmaf(__half2float(hb.x), w3s[4*i + c], sum);
                    sum = fmaf(__half2float(hb.y), w3s[4*i + 2 + c], sum);
                }
                s_pr[2*rI + c] = sum;
            }
            __syncthreads();

            if (t < 2*NPTS) {
                const int pp = t >> 1, c = t & 1;
                const int rb = pp*4;
                float a0 = s_area[rb+0], a1 = s_area[rb+1], a2 = s_area[rb+2], a3 = s_area[rb+3];
                float tot = a0 + a1 + a2 + a3;
                float v = s_pr[2*(rb+0)+c]*a3 + s_pr[2*(rb+1)+c]*a2
                        + s_pr[2*(rb+2)+c]*a1 + s_pr[2*(rb+3)+c]*a0;
                v /= tot;
                const int g = g0 + pp;
                const int bb2 = g >> 15, q = g & (Q_ - 1);
                const int oidx = (bb2*2 + c)*Q_ + q;
                out[oidx] = v + coarse[oidx];
            }
            __syncthreads();
        }
    }
}

// ---------------- launch ----------------
extern "C" void kernel_launch(void* const* d_in, const int* in_sizes, int n_in,
                              void* d_out, int out_size) {
    const float* feat    = (const float*)d_in[0];
    const float* pcoords = (const float*)d_in[1];
    const float* coarse  = (const float*)d_in[2];
    const float* coef_w  = (const float*)d_in[4];
    const float* coef_b  = (const float*)d_in[5];
    const float* freq_w  = (const float*)d_in[6];
    const float* freq_b  = (const float*)d_in[7];
    const float* phase_w = (const float*)d_in[8];
    const float* b0 = (const float*)d_in[10];
    const float* b1 = (const float*)d_in[12];
    const float* b2 = (const float*)d_in[14];
    const float* w3 = (const float*)d_in[15];
    const float* b3 = (const float*)d_in[16];
    float* out = (float*)d_out;

    prep_feat<<<dim3(32, 128, 2), dim3(32, 8)>>>(feat);
    border_zero<<<(B_*HP*HP + 255)/256, 256>>>();
    prep_wconv<<<(512*2304 + 255)/256, 256>>>(coef_w, coef_b, freq_w, freq_b);
    prep_wmlp<<<(3*65536 + 255)/256, 256>>>((const float*)d_in[9], (const float*)d_in[11],
                                            (const float*)d_in[13]);

    const int FSMEM = 3*ST_SZ*2;       // 184320 B
    cudaFuncSetAttribute(fused_kernel, cudaFuncAttributeMaxDynamicSharedMemorySize, FSMEM);
    fused_kernel<<<148, 512, FSMEM>>>(pcoords, phase_w, b0, b1, b2, w3, b3,
                                      coarse, out);
}

// round 14
// speedup vs baseline: 1.1470x; 1.1470x over previous
#include <cuda_runtime.h>
#include <cuda_bf16.h>
#include <cuda_fp16.h>
#include <cstdint>
#include <cstddef>

#define B_ 2
#define C_ 256
#define H_ 128
#define W_ 128
#define Q_ 32768
#define HP 130
#define HW_ (H_*W_)

// ---------------- static device scratch ----------------
__device__ __align__(16) __half g_Ah[(size_t)B_*HP*HP*C_];   // padded NHWC hi (fp16)
__device__ __align__(16) __half g_Al[(size_t)B_*HP*HP*C_];   // padded NHWC lo (fp16)
__device__ __align__(16) __half g_Wth[512*2304];             // conv W^T [oc][k] hi
__device__ __align__(16) __half g_Wtl[512*2304];             // lo
__device__ __align__(16) __half g_Mh[3*256*256];             // mlp W^T [l][n][k] fp16
__device__ float g_cbias[512];
__device__ __align__(16) float g_cf[(size_t)B_*HW_*512];     // conv out [b][pix][512] fp32

// ---------------- helpers ----------------
__device__ __forceinline__ uint32_t smem_u32(const void* p){
    return (uint32_t)__cvta_generic_to_shared(p);
}
__device__ __forceinline__ void ldsm4(uint32_t& r0,uint32_t& r1,uint32_t& r2,uint32_t& r3,uint32_t a){
    asm volatile("ldmatrix.sync.aligned.m8n8.x4.shared.b16 {%0,%1,%2,%3},[%4];"
        :"=r"(r0),"=r"(r1),"=r"(r2),"=r"(r3):"r"(a));
}
__device__ __forceinline__ void cp16(uint32_t d, const void* s){
    asm volatile("cp.async.ca.shared.global [%0],[%1],16;"::"r"(d),"l"(s));
}
__device__ __forceinline__ void cp_commit(){ asm volatile("cp.async.commit_group;"); }
__device__ __forceinline__ void mma16816h(float* c, const uint32_t* a, const uint32_t* b){
    asm volatile("mma.sync.aligned.m16n8k16.row.col.f32.f16.f16.f32 "
        "{%0,%1,%2,%3},{%4,%5,%6,%7},{%8,%9},{%0,%1,%2,%3};"
        : "+f"(c[0]),"+f"(c[1]),"+f"(c[2]),"+f"(c[3])
        : "r"(a[0]),"r"(a[1]),"r"(a[2]),"r"(a[3]),"r"(b[0]),"r"(b[1]));
}
__device__ __forceinline__ uint32_t pack_hi16(float2 v){
    __half2 h = __floats2half2_rn(v.x, v.y);
    return *reinterpret_cast<uint32_t*>(&h);
}
// fast sin/cos of pi*x (abs err < 4e-6)
__device__ __forceinline__ void sincospif_fast(float x, float* sp, float* cp){
    float n = rintf(x);
    float r = x - n;
    float r2 = r*r;
    float s = fmaf(r2, 0.08214588661f, -0.5992645293f);
    s = fmaf(r2, s, 2.550164040f);
    s = fmaf(r2, s, -5.167712780f);
    s = fmaf(r2, s, 3.14159265359f);
    s *= r;
    float c = fmaf(r2, -0.02580689139f, 0.2353306304f);
    c = fmaf(r2, c, -1.335262769f);
    c = fmaf(r2, c, 4.058712126f);
    c = fmaf(r2, c, -4.934802201f);
    c = fmaf(r2, c, 1.0f);
    uint32_t sg = ((uint32_t)(int)n) << 31;
    *sp = __uint_as_float(__float_as_uint(s) ^ sg);
    *cp = __uint_as_float(__float_as_uint(c) ^ sg);
}

// ---------------- prep kernels ----------------
__global__ void prep_feat(const float* __restrict__ feat){
    __shared__ float tile[32][33];
    const int bx = blockIdx.x;
    const int cg = bx >> 2, xg = bx & 3;
    const int y = blockIdx.y, b = blockIdx.z;
    const int tx = threadIdx.x, ty = threadIdx.y;
    #pragma unroll
    for (int k = 0; k < 4; ++k){
        int c = cg*32 + ty + k*8;
        int x = xg*32 + tx;
        tile[ty + k*8][tx] = feat[(((size_t)(b*C_ + c))*H_ + y)*W_ + x];
    }
    __syncthreads();
    #pragma unroll
    for (int k = 0; k < 4; ++k){
        int c = cg*32 + tx;
        int x = xg*32 + ty + k*8;
        float v = tile[tx][ty + k*8];
        __half h = __float2half_rn(v);
        size_t o = ((size_t)((b*HP + y + 1)*HP + x + 1))*C_ + c;
        g_Ah[o] = h;
        g_Al[o] = __float2half_rn(v - __half2float(h));
    }
}

__global__ void border_zero(){
    int id = blockIdx.x*256 + threadIdx.x;
    if (id >= B_*HP*HP) return;
    int xx = id % HP, rest = id / HP;
    int yy = rest % HP;
    if (yy >= 1 && yy <= H_ && xx >= 1 && xx <= W_) return;
    uint4 z = make_uint4(0,0,0,0);
    uint4* ph = (uint4*)(g_Ah + (size_t)id*C_);
    uint4* pl = (uint4*)(g_Al + (size_t)id*C_);
    #pragma unroll
    for (int i = 0; i < 32; ++i){ ph[i] = z; pl[i] = z; }
}

__global__ void prep_wconv(const float* __restrict__ cw, const float* __restrict__ cb,
                           const float* __restrict__ fw, const float* __restrict__ fb){
    int id = blockIdx.x*256 + threadIdx.x;
    if (id < 512) g_cbias[id] = (id < 256) ? cb[id] : fb[id-256];
    if (id >= 512*2304) return;
    int oc = id / 2304, k = id % 2304;
    int tap = k >> 8, ic = k & 255;
    float v = (oc < 256) ? cw[(oc*256 + ic)*9 + tap]
                         : fw[((oc-256)*256 + ic)*9 + tap];
    __half h = __float2half_rn(v);
    g_Wth[id] = h;
    g_Wtl[id] = __float2half_rn(v - __half2float(h));
}

__global__ void prep_wmlp(const float* __restrict__ w0, const float* __restrict__ w1,
                          const float* __restrict__ w2){
    int id = blockIdx.x*256 + threadIdx.x;
    if (id >= 3*65536) return;
    int l = id >> 16, r = id & 65535;
    int n = r >> 8, k = r & 255;
    const float* w = (l==0) ? w0 : (l==1) ? w1 : w2;
    g_Mh[id] = __float2half_rn(w[k*256 + n]);
}

// ---------------- conv: R11 (128px x 256oc, 3-stage, freq-first), hoisted addresses ----------------
#define ST_AH 0
#define ST_AL 5120
#define ST_BH 10240
#define ST_BL 20480
#define ST_SZ 30720                 // halves per stage (61440 B)
__global__ __launch_bounds__(256) void conv_mma_kernel(){
    extern __shared__ __align__(16) __half cs[];
    const int t = threadIdx.x, warp = t>>5, lane = t&31;
    const int y = blockIdx.x, b = blockIdx.y;
    const bool three = (blockIdx.z == 0);
    const int oc0 = three ? 256 : 0;
    const int m0 = (warp>>2)*64, n0 = (warp&3)*64;
    const int rsel = lane & 15, kgrp = (lane >> 4)*8;

    float acc[4][8][4];
    #pragma unroll
    for (int i=0;i<4;++i)
        #pragma unroll
        for (int j=0;j<8;++j)
            #pragma unroll
            for (int q=0;q<4;++q) acc[i][j][q] = 0.f;

    // hoisted per-warp ldsm byte offsets (within one stage buffer)
    const uint32_t csb = smem_u32(cs);
    uint32_t aoff_h[4], aoff_l[4], boff_h[4], boff_l[4];
    #pragma unroll
    for (int mi=0;mi<4;++mi){
        aoff_h[mi] = (uint32_t)(ST_AH + (m0+mi*16+rsel)*40 + kgrp)*2;
        aoff_l[mi] = (uint32_t)(ST_AL + (m0+mi*16+rsel)*40 + kgrp)*2;
    }
    #pragma unroll
    for (int nj=0;nj<4;++nj){
        boff_h[nj] = (uint32_t)(ST_BH + (n0+nj*16+rsel)*40 + kgrp)*2;
        boff_l[nj] = (uint32_t)(ST_BL + (n0+nj*16+rsel)*40 + kgrp)*2;
    }

    auto issue = [&](int s, int buf){
        const int tap = s >> 3, sub = s & 7;
        const int ky = tap/3, kx = tap - ky*3;
        const int k0 = tap*256 + sub*32;
        __half* dstb = cs + buf*ST_SZ;
        #pragma unroll
        for (int j=0;j<12;++j){
            if (j>=2 && j<4 && !three) continue;     // Al only for freq
            if (j>=8 && !three) continue;            // Bl only for freq
            int cid = t + j*256;
            uint32_t dst; const __half* src;
            if (j < 4){
                int w = cid & 511, row = w >> 2, ch = w & 3;
                const __half* base = (j < 2) ? g_Ah : g_Al;
                src = base + ((size_t)((b*HP + y+ky)*HP + row + kx))*C_ + sub*32 + ch*8;
                dst = smem_u32(dstb + ((j<2)?ST_AH:ST_AL) + row*40 + ch*8);
            } else {
                int w = cid & 1023, row = w >> 2, ch = w & 3;
                const __half* base = (j < 8) ? g_Wth : g_Wtl;
                src = base + (size_t)(oc0 + row)*2304 + k0 + ch*8;
                dst = smem_u32(dstb + ((j<8)?ST_BH:ST_BL) + row*40 + ch*8);
            }
            cp16(dst, src);
        }
        cp_commit();
    };

    issue(0, 0); issue(1, 1);
    asm volatile("cp.async.wait_group 1;");
    __syncthreads();

    for (int s = 0; s < 72; ++s){
        const int buf = s % 3;
        if (s + 2 < 72) issue(s + 2, (s + 2) % 3);
        const uint32_t bb0 = csb + (uint32_t)buf*(ST_SZ*2);
        #pragma unroll
        for (int k16 = 0; k16 < 32; k16 += 16){
            const uint32_t kb = bb0 + (uint32_t)k16*2;
            uint32_t ah[4][4], al[4][4];
            #pragma unroll
            for (int mi=0;mi<4;++mi){
                ldsm4(ah[mi][0],ah[mi][1],ah[mi][2],ah[mi][3], kb + aoff_h[mi]);
                if (three)
                    ldsm4(al[mi][0],al[mi][1],al[mi][2],al[mi][3], kb + aoff_l[mi]);
            }
            #pragma unroll
            for (int nj=0;nj<4;++nj){
                uint32_t r0,r1,r2,r3;
                ldsm4(r0,r1,r2,r3, kb + boff_h[nj]);
                uint32_t bh0[2] = {r0, r2}, bh1[2] = {r1, r3};
                if (three){
                    uint32_t q0,q1,q2,q3;
                    ldsm4(q0,q1,q2,q3, kb + boff_l[nj]);
                    uint32_t bl0[2] = {q0, q2}, bl1[2] = {q1, q3};
                    #pragma unroll
                    for (int mi=0;mi<4;++mi){
                        mma16816h(acc[mi][2*nj],   ah[mi], bh0);
                        mma16816h(acc[mi][2*nj],   al[mi], bh0);
                        mma16816h(acc[mi][2*nj],   ah[mi], bl0);
                        mma16816h(acc[mi][2*nj+1], ah[mi], bh1);
                        mma16816h(acc[mi][2*nj+1], al[mi], bh1);
                        mma16816h(acc[mi][2*nj+1], ah[mi], bl1);
                    }
                } else {
                    #pragma unroll
                    for (int mi=0;mi<4;++mi){
                        mma16816h(acc[mi][2*nj],   ah[mi], bh0);
                        mma16816h(acc[mi][2*nj+1], ah[mi], bh1);
                    }
                }
            }
        }
        if (s < 71){
            if (s + 2 < 72) asm volatile("cp.async.wait_group 1;");
            else            asm volatile("cp.async.wait_group 0;");
            __syncthreads();
        }
    }

    #pragma unroll
    for (int mi=0;mi<4;++mi){
        const int x = m0 + mi*16 + (lane>>2);
        #pragma unroll
        for (int ni=0;ni<8;++ni){
            const int col = oc0 + n0 + ni*8 + (lane&3)*2;
            float2 bb = *(const float2*)&g_cbias[col];
            float* o0 = g_cf + ((size_t)(b*HW_ + y*W_ + x))*512 + col;
            float* o1 = g_cf + ((size_t)(b*HW_ + y*W_ + x + 8))*512 + col;
            *(float2*)o0 = make_float2(acc[mi][ni][0]+bb.x, acc[mi][ni][1]+bb.y);
            *(float2*)o1 = make_float2(acc[mi][ni][2]+bb.x, acc[mi][ni][3]+bb.y);
        }
    }
}

// ---------------- point kernel: 512 threads, warp tile 32x64, K chunks of 128 (6 stages) ----------------
#define MROWS 128
#define NPTS  32
#define XP    264                 // fp16 pitch for X rows
#define WP3   136                 // fp16 pitch for 128-k weight chunk rows (272B)
#define WSTG3 (256*WP3)           // fp16 elems per stage
__global__ __launch_bounds__(512) void point_mma_kernel(
        const float* __restrict__ pc,
        const float* __restrict__ phase_w,
        const float* __restrict__ b0, const float* __restrict__ b1,
        const float* __restrict__ b2,
        const float* __restrict__ w3, const float* __restrict__ b3,
        const float* __restrict__ coarse,
        float* __restrict__ out) {
    extern __shared__ __align__(16) __half smh[];
    __half* Xh = smh;                          // 128*264
    __half* Wt = Xh + MROWS*XP;                // 2 stages * WSTG3
    float* misc  = (float*)(Wt + 2*WSTG3);
    float* ph     = misc;                  // 256
    float* s_rel0 = ph + 256;              // 128
    float* s_rel1 = s_rel0 + 128;          // 128
    float* s_area = s_rel1 + 128;          // 128
    int*   s_pix  = (int*)(s_area + 128);  // 128
    int*   s_phof = s_pix + 128;           // 128
    float* w3s    = (float*)(s_phof + 128);// 514
    float* s_pr   = w3s + 514;             // 256

    const int t = threadIdx.x, warp = t>>5, lane = t&31;
    const int g0 = blockIdx.x * NPTS;
    const int m0 = (warp>>2)*32, n0 = (warp&3)*64;
    const int rsel = lane & 15, kgrp = (lane >> 4)*8;

    if (t < 128) {
        float p0 = phase_w[2*t], p1 = phase_w[2*t+1];
        ph[t]       = fmaf(8.f,   p0, 8.f*p1);
        ph[128 + t] = fmaf(128.f, p0, 128.f*p1);
    }
    for (int i = t; i < 514; i += 512)
        w3s[i] = (i < 512) ? w3[i] : b3[i - 512];

    if (t < MROWS) {
        const int p_local = t >> 2, s = t & 3;
        const int g = g0 + p_local;
        const int q = g & (Q_ - 1);
        const float pc0 = pc[2*g], pc1 = pc[2*g + 1];
        const float SH_P = (float)( 1.0/128.0 + 1e-6);
        const float SH_M = (float)(-1.0/128.0 + 1e-6);
        const float LO = (float)(-1.0 + 1e-6), HI = (float)(1.0 - 1e-6);
        float cy = pc0 + ((s >= 2) ? SH_P : SH_M);
        float cx = pc1 + ((s & 1) ? SH_P : SH_M);
        cy = fminf(fmaxf(cy, LO), HI);
        cx = fminf(fmaxf(cx, LO), HI);
        int iy = (int)rintf(((cy + 1.f)*128.f - 1.f)*0.5f);
        int ix = (int)rintf(((cx + 1.f)*128.f - 1.f)*0.5f);
        iy = min(max(iy, 0), 127); ix = min(max(ix, 0), 127);
        float qcy = -0.9921875f + 0.015625f*(float)iy;
        float qcx = -0.9921875f + 0.015625f*(float)ix;
        float rel0 = (pc0 - qcy)*128.f;
        float rel1 = (pc1 - qcx)*128.f;
        s_pix[t]  = iy*W_ + ix;
        s_rel0[t] = rel0;  s_rel1[t] = rel1;
        s_area[t] = fabsf(rel0*rel1) + 1e-9f;
        s_phof[t] = (q < 2) ? 0 : 128;
    }
    __syncthreads();

    // weight prefetch: 6 chunks of k=128 (3 layers x 2)
    auto wissue = [&](int g, int stg){
        const int L = g >> 1, kc = g & 1;
        __half* dstb = Wt + stg*WSTG3;
        const __half* srcb = g_Mh + L*65536 + kc*128;
        #pragma unroll
        for (int j=0;j<8;++j){
            int cid = t + j*512;            // 0..4095
            int row = cid >> 4, ch = cid & 15;
            cp16(smem_u32(dstb + row*WP3 + ch*8), srcb + row*256 + ch*8);
        }
        cp_commit();
    };
    wissue(0, 0);

    // gather + sinusoidal features -> Xh (fp16)
    {
        #pragma unroll 1
        for (int rr = 0; rr < 8; ++rr) {
            const int r = warp*8 + rr;
            const int g = g0 + (r >> 2);
            const int bb = g >> 15;
            const float* base = g_cf + ((size_t)(bb*HW_ + s_pix[r])) * 512;
            const float rel0 = s_rel0[r], rel1 = s_rel1[r];
            const float* php = ph + s_phof[r];
            #pragma unroll
            for (int i = 0; i < 2; ++i) {
                const int kp = lane + 32*i;
                const int k0 = 2*kp;
                float4 f4 = *(const float4*)(base + 256 + 2*k0);
                float2 cc = *(const float2*)(base + k0);
                float2 cs2 = *(const float2*)(base + 128 + k0);
                float2 ph2 = *(const float2*)(php + k0);
                float qf0 = fmaf(f4.x, rel0, fmaf(f4.y, rel1, ph2.x));
                float qf1 = fmaf(f4.z, rel0, fmaf(f4.w, rel1, ph2.y));
                float sv0, cv0, sv1, cv1;
                sincospif_fast(qf0, &sv0, &cv0);
                sincospif_fast(qf1, &sv1, &cv1);
                *(uint32_t*)&Xh[r*XP + k0]       = pack_hi16(make_float2(cc.x*cv0,  cc.y*cv1));
                *(uint32_t*)&Xh[r*XP + 128 + k0] = pack_hi16(make_float2(cs2.x*sv0, cs2.y*sv1));
            }
        }
    }
    asm volatile("cp.async.wait_group 0;");
    __syncthreads();    // X visible + W(0) visible

    // 6 stages (3 layers x 2 k-chunks of 128)
    float acc[2][8][4];
    for (int g = 0; g < 6; ++g){
        const int L = g >> 1, kc = g & 1, stg = g & 1;
        if (kc == 0){
            #pragma unroll
            for (int i=0;i<2;++i)
                #pragma unroll
                for (int j=0;j<8;++j)
                    #pragma unroll
                    for (int q=0;q<4;++q) acc[i][j][q] = 0.f;
        }
        if (g+1 < 6) wissue(g+1, (g+1)&1);

        const __half* WH = Wt + stg*WSTG3;
        #pragma unroll
        for (int kh = 0; kh < 8; ++kh){
            const int k16 = kc*128 + kh*16;
            uint32_t AH[2][4];
            #pragma unroll
            for (int mi=0;mi<2;++mi){
                ldsm4(AH[mi][0],AH[mi][1],AH[mi][2],AH[mi][3],
                      smem_u32(Xh + (m0+mi*16+rsel)*XP + k16 + kgrp));
            }
            #pragma unroll
            for (int nj=0;nj<4;++nj){
                uint32_t r0,r1,r2,r3;
                ldsm4(r0,r1,r2,r3, smem_u32(WH + (n0+nj*16+rsel)*WP3 + kh*16 + kgrp));
                uint32_t b0r[2] = {r0, r2}, b1r[2] = {r1, r3};
                #pragma unroll
                for (int mi=0;mi<2;++mi){
                    mma16816h(acc[mi][2*nj],   AH[mi], b0r);
                    mma16816h(acc[mi][2*nj+1], AH[mi], b1r);
                }
            }
        }

        if (kc == 1){
            __syncthreads();   // all X reads of this layer done before overwrite
            const float* bg = (L==0) ? b0 : (L==1) ? b1 : b2;
            #pragma unroll
            for (int mi=0;mi<2;++mi){
                const int r = m0 + mi*16 + (lane>>2);
                #pragma unroll
                for (int ni=0;ni<8;++ni){
                    const int c = n0 + ni*8 + (lane&3)*2;
                    float2 bb = *(const float2*)&bg[c];
                    *(uint32_t*)&Xh[r*XP + c] =
                        pack_hi16(make_float2(fmaxf(acc[mi][ni][0]+bb.x, 0.f),
                                              fmaxf(acc[mi][ni][1]+bb.y, 0.f)));
                    *(uint32_t*)&Xh[(r+8)*XP + c] =
                        pack_hi16(make_float2(fmaxf(acc[mi][ni][2]+bb.x, 0.f),
                                              fmaxf(acc[mi][ni][3]+bb.y, 0.f)));
                }
            }
        }
        asm volatile("cp.async.wait_group 0;");
        __syncthreads();
    }

    // final 256->2 layer (fp32 accum from fp16 activations)
    if (t < 2*MROWS) {
        const int r = t >> 1, c = t & 1;
        const __half* rh = Xh + r*XP;
        float sum = w3s[512 + c];
        #pragma unroll 4
        for (int i = 0; i < 128; ++i) {
            uint32_t hu = *(const uint32_t*)&rh[2*i];
            __half2 hb = *reinterpret_cast<__half2*>(&hu);
            sum = fmaf(__half2float(hb.x), w3s[4*i + c], sum);
            sum = fmaf(__half2float(hb.y), w3s[4*i + 2 + c], sum);
        }
        s_pr[2*r + c] = sum;
    }
    __syncthreads();

    // local-ensemble combine + coarse residual
    if (t < 2*NPTS) {
        const int p = t >> 1, c = t & 1;
        const int rb = p*4;
        float a0 = s_area[rb+0], a1 = s_area[rb+1], a2 = s_area[rb+2], a3 = s_area[rb+3];
        float tot = a0 + a1 + a2 + a3;
        float v = s_pr[2*(rb+0)+c]*a3 + s_pr[2*(rb+1)+c]*a2
                + s_pr[2*(rb+2)+c]*a1 + s_pr[2*(rb+3)+c]*a0;
        v /= tot;
        const int g = g0 + p;
        const int bb = g >> 15, q = g & (Q_ - 1);
        const int oidx = (bb*2 + c)*Q_ + q;
        out[oidx] = v + coarse[oidx];
    }
}

// ---------------- launch ----------------
extern "C" void kernel_launch(void* const* d_in, const int* in_sizes, int n_in,
                              void* d_out, int out_size) {
    const float* feat    = (const float*)d_in[0];
    const float* pcoords = (const float*)d_in[1];
    const float* coarse  = (const float*)d_in[2];
    const float* coef_w  = (const float*)d_in[4];
    const float* coef_b  = (const float*)d_in[5];
    const float* freq_w  = (const float*)d_in[6];
    const float* freq_b  = (const float*)d_in[7];
    const float* phase_w = (const float*)d_in[8];
    const float* b0 = (const float*)d_in[10];
    const float* b1 = (const float*)d_in[12];
    const float* b2 = (const float*)d_in[14];
    const float* w3 = (const float*)d_in[15];
    const float* b3 = (const float*)d_in[16];
    float* out = (float*)d_out;

    prep_feat<<<dim3(32, 128, 2), dim3(32, 8)>>>(feat);
    border_zero<<<(B_*HP*HP + 255)/256, 256>>>();
    prep_wconv<<<(512*2304 + 255)/256, 256>>>(coef_w, coef_b, freq_w, freq_b);
    prep_wmlp<<<(3*65536 + 255)/256, 256>>>((const float*)d_in[9], (const float*)d_in[11],
                                            (const float*)d_in[13]);

    const int CSMEM = 3*ST_SZ*2;       // 184320 B
    cudaFuncSetAttribute(conv_mma_kernel, cudaFuncAttributeMaxDynamicSharedMemorySize, CSMEM);
    conv_mma_kernel<<<dim3(128, 2, 2), 256, CSMEM>>>();

    const int PSMEM = (MROWS*XP)*2 + (2*WSTG3)*2
                    + (256 + 128*3 + 514 + 256)*4 + 128*2*4 + 64;
    cudaFuncSetAttribute(point_mma_kernel, cudaFuncAttributeMaxDynamicSharedMemorySize, PSMEM);
    point_mma_kernel<<<(B_*Q_)/NPTS, 512, PSMEM>>>(pcoords, phase_w,
                                                   b0, b1, b2, w3, b3,
                                                   coarse, out);
}

// round 16
// speedup vs baseline: 1.2688x; 1.1062x over previous
#include <cuda_runtime.h>
#include <cuda_bf16.h>
#include <cuda_fp16.h>
#include <cstdint>
#include <cstddef>

#define B_ 2
#define C_ 256
#define H_ 128
#define W_ 128
#define Q_ 32768
#define HP 130
#define HW_ (H_*W_)

// ---------------- static device scratch ----------------
__device__ __align__(16) __half g_Ah[(size_t)B_*HP*HP*C_];   // padded NHWC hi (fp16)
__device__ __align__(16) __half g_Al[(size_t)B_*HP*HP*C_];   // padded NHWC lo (fp16)
__device__ __align__(16) __half g_Wth[512*2304];             // conv W^T [oc][k] fp16 (hi only)
__device__ __align__(16) __half g_Mh[3*256*256];             // mlp W^T [l][n][k] fp16
__device__ float g_cbias[512];
__device__ __align__(16) float g_cf[(size_t)B_*HW_*512];     // conv out [b][pix][512] fp32

// ---------------- helpers ----------------
__device__ __forceinline__ uint32_t smem_u32(const void* p){
    return (uint32_t)__cvta_generic_to_shared(p);
}
__device__ __forceinline__ void ldsm4(uint32_t& r0,uint32_t& r1,uint32_t& r2,uint32_t& r3,uint32_t a){
    asm volatile("ldmatrix.sync.aligned.m8n8.x4.shared.b16 {%0,%1,%2,%3},[%4];"
        :"=r"(r0),"=r"(r1),"=r"(r2),"=r"(r3):"r"(a));
}
__device__ __forceinline__ void cp16(uint32_t d, const void* s){
    asm volatile("cp.async.ca.shared.global [%0],[%1],16;"::"r"(d),"l"(s));
}
__device__ __forceinline__ void cp_commit(){ asm volatile("cp.async.commit_group;"); }
__device__ __forceinline__ void mma16816h(float* c, const uint32_t* a, const uint32_t* b){
    asm volatile("mma.sync.aligned.m16n8k16.row.col.f32.f16.f16.f32 "
        "{%0,%1,%2,%3},{%4,%5,%6,%7},{%8,%9},{%0,%1,%2,%3};"
        : "+f"(c[0]),"+f"(c[1]),"+f"(c[2]),"+f"(c[3])
        : "r"(a[0]),"r"(a[1]),"r"(a[2]),"r"(a[3]),"r"(b[0]),"r"(b[1]));
}
__device__ __forceinline__ uint32_t pack_hi16(float2 v){
    __half2 h = __floats2half2_rn(v.x, v.y);
    return *reinterpret_cast<uint32_t*>(&h);
}
// fast sin/cos of pi*x (abs err < 4e-6)
__device__ __forceinline__ void sincospif_fast(float x, float* sp, float* cp){
    float n = rintf(x);
    float r = x - n;
    float r2 = r*r;
    float s = fmaf(r2, 0.08214588661f, -0.5992645293f);
    s = fmaf(r2, s, 2.550164040f);
    s = fmaf(r2, s, -5.167712780f);
    s = fmaf(r2, s, 3.14159265359f);
    s *= r;
    float c = fmaf(r2, -0.02580689139f, 0.2353306304f);
    c = fmaf(r2, c, -1.335262769f);
    c = fmaf(r2, c, 4.058712126f);
    c = fmaf(r2, c, -4.934802201f);
    c = fmaf(r2, c, 1.0f);
    uint32_t sg = ((uint32_t)(int)n) << 31;
    *sp = __uint_as_float(__float_as_uint(s) ^ sg);
    *cp = __uint_as_float(__float_as_uint(c) ^ sg);
}

// ---------------- prep kernels ----------------
__global__ void prep_feat(const float* __restrict__ feat){
    __shared__ float tile[32][33];
    const int bx = blockIdx.x;
    const int cg = bx >> 2, xg = bx & 3;
    const int y = blockIdx.y, b = blockIdx.z;
    const int tx = threadIdx.x, ty = threadIdx.y;
    #pragma unroll
    for (int k = 0; k < 4; ++k){
        int c = cg*32 + ty + k*8;
        int x = xg*32 + tx;
        tile[ty + k*8][tx] = feat[(((size_t)(b*C_ + c))*H_ + y)*W_ + x];
    }
    __syncthreads();
    #pragma unroll
    for (int k = 0; k < 4; ++k){
        int c = cg*32 + tx;
        int x = xg*32 + ty + k*8;
        float v = tile[tx][ty + k*8];
        __half h = __float2half_rn(v);
        size_t o = ((size_t)((b*HP + y + 1)*HP + x + 1))*C_ + c;
        g_Ah[o] = h;
        g_Al[o] = __float2half_rn(v - __half2float(h));
    }
}

__global__ void border_zero(){
    int id = blockIdx.x*256 + threadIdx.x;
    if (id >= B_*HP*HP) return;
    int xx = id % HP, rest = id / HP;
    int yy = rest % HP;
    if (yy >= 1 && yy <= H_ && xx >= 1 && xx <= W_) return;
    uint4 z = make_uint4(0,0,0,0);
    uint4* ph = (uint4*)(g_Ah + (size_t)id*C_);
    uint4* pl = (uint4*)(g_Al + (size_t)id*C_);
    #pragma unroll
    for (int i = 0; i < 32; ++i){ ph[i] = z; pl[i] = z; }
}

__global__ void prep_wconv(const float* __restrict__ cw, const float* __restrict__ cb,
                           const float* __restrict__ fw, const float* __restrict__ fb){
    int id = blockIdx.x*256 + threadIdx.x;
    if (id < 512) g_cbias[id] = (id < 256) ? cb[id] : fb[id-256];
    if (id >= 512*2304) return;
    int oc = id / 2304, k = id % 2304;
    int tap = k >> 8, ic = k & 255;
    float v = (oc < 256) ? cw[(oc*256 + ic)*9 + tap]
                         : fw[((oc-256)*256 + ic)*9 + tap];
    g_Wth[id] = __float2half_rn(v);
}

__global__ void prep_wmlp(const float* __restrict__ w0, const float* __restrict__ w1,
                          const float* __restrict__ w2){
    int id = blockIdx.x*256 + threadIdx.x;
    if (id >= 3*65536) return;
    int l = id >> 16, r = id & 65535;
    int n = r >> 8, k = r & 255;
    const float* w = (l==0) ? w0 : (l==1) ? w1 : w2;
    g_Mh[id] = __float2half_rn(w[k*256 + n]);
}

// ---------------- conv: 128px x 256oc, 3-stage, freq-first ----------------
// z=0 -> freq (2-term: Ah*Bh + Al*Bh), z=1 -> coef (1-term: Ah*Bh)
#define ST_AH 0
#define ST_AL 5120
#define ST_BH 10240
#define ST_SZ 20480                 // halves per stage (40960 B); 3 stages = 122880 B
__global__ __launch_bounds__(256) void conv_mma_kernel(){
    extern __shared__ __align__(16) __half cs[];
    const int t = threadIdx.x, warp = t>>5, lane = t&31;
    const int y = blockIdx.x, b = blockIdx.y;
    const bool two = (blockIdx.z == 0);      // freq half: 2-term
    const int oc0 = two ? 256 : 0;
    const int m0 = (warp>>2)*64, n0 = (warp&3)*64;
    const int rsel = lane & 15, kgrp = (lane >> 4)*8;

    float acc[4][8][4];
    #pragma unroll
    for (int i=0;i<4;++i)
        #pragma unroll
        for (int j=0;j<8;++j)
            #pragma unroll
            for (int q=0;q<4;++q) acc[i][j][q] = 0.f;

    const uint32_t csb = smem_u32(cs);
    uint32_t aoff_h[4], aoff_l[4], boff_h[4];
    #pragma unroll
    for (int mi=0;mi<4;++mi){
        aoff_h[mi] = (uint32_t)(ST_AH + (m0+mi*16+rsel)*40 + kgrp)*2;
        aoff_l[mi] = (uint32_t)(ST_AL + (m0+mi*16+rsel)*40 + kgrp)*2;
    }
    #pragma unroll
    for (int nj=0;nj<4;++nj)
        boff_h[nj] = (uint32_t)(ST_BH + (n0+nj*16+rsel)*40 + kgrp)*2;

    auto issue = [&](int s, int buf){
        const int tap = s >> 3, sub = s & 7;
        const int ky = tap/3, kx = tap - ky*3;
        const int k0 = tap*256 + sub*32;
        __half* dstb = cs + buf*ST_SZ;
        #pragma unroll
        for (int j=0;j<8;++j){
            if (j>=2 && j<4 && !two) continue;       // Al only for freq
            int cid = t + j*256;
            uint32_t dst; const __half* src;
            if (j < 4){
                int w = cid & 511, row = w >> 2, ch = w & 3;
                const __half* base = (j < 2) ? g_Ah : g_Al;
                src = base + ((size_t)((b*HP + y+ky)*HP + row + kx))*C_ + sub*32 + ch*8;
                dst = smem_u32(dstb + ((j<2)?ST_AH:ST_AL) + row*40 + ch*8);
            } else {
                int w = cid & 1023, row = w >> 2, ch = w & 3;
                src = g_Wth + (size_t)(oc0 + row)*2304 + k0 + ch*8;
                dst = smem_u32(dstb + ST_BH + row*40 + ch*8);
            }
            cp16(dst, src);
        }
        cp_commit();
    };

    issue(0, 0); issue(1, 1);
    asm volatile("cp.async.wait_group 1;");
    __syncthreads();

    #pragma unroll 1
    for (int s = 0; s < 72; ++s){
        const int buf = s % 3;
        if (s + 2 < 72) issue(s + 2, (s + 2) % 3);
        const uint32_t bb0 = csb + (uint32_t)buf*(ST_SZ*2);
        #pragma unroll
        for (int k16 = 0; k16 < 32; k16 += 16){
            const uint32_t kb = bb0 + (uint32_t)k16*2;
            uint32_t ah[4][4], al[4][4];
            #pragma unroll
            for (int mi=0;mi<4;++mi){
                ldsm4(ah[mi][0],ah[mi][1],ah[mi][2],ah[mi][3], kb + aoff_h[mi]);
                if (two)
                    ldsm4(al[mi][0],al[mi][1],al[mi][2],al[mi][3], kb + aoff_l[mi]);
            }
            #pragma unroll
            for (int nj=0;nj<4;++nj){
                uint32_t r0,r1,r2,r3;
                ldsm4(r0,r1,r2,r3, kb + boff_h[nj]);
                uint32_t bh0[2] = {r0, r2}, bh1[2] = {r1, r3};
                if (two){
                    #pragma unroll
                    for (int mi=0;mi<4;++mi){
                        mma16816h(acc[mi][2*nj],   ah[mi], bh0);
                        mma16816h(acc[mi][2*nj],   al[mi], bh0);
                        mma16816h(acc[mi][2*nj+1], ah[mi], bh1);
                        mma16816h(acc[mi][2*nj+1], al[mi], bh1);
                    }
                } else {
                    #pragma unroll
                    for (int mi=0;mi<4;++mi){
                        mma16816h(acc[mi][2*nj],   ah[mi], bh0);
                        mma16816h(acc[mi][2*nj+1], ah[mi], bh1);
                    }
                }
            }
        }
        if (s < 71){
            if (s + 2 < 72) asm volatile("cp.async.wait_group 1;");
            else            asm volatile("cp.async.wait_group 0;");
            __syncthreads();
        }
    }

    #pragma unroll
    for (int mi=0;mi<4;++mi){
        const int x = m0 + mi*16 + (lane>>2);
        #pragma unroll
        for (int ni=0;ni<8;++ni){
            const int col = oc0 + n0 + ni*8 + (lane&3)*2;
            float2 bb = *(const float2*)&g_cbias[col];
            float* o0 = g_cf + ((size_t)(b*HW_ + y*W_ + x))*512 + col;
            float* o1 = g_cf + ((size_t)(b*HW_ + y*W_ + x + 8))*512 + col;
            *(float2*)o0 = make_float2(acc[mi][ni][0]+bb.x, acc[mi][ni][1]+bb.y);
            *(float2*)o1 = make_float2(acc[mi][ni][2]+bb.x, acc[mi][ni][3]+bb.y);
        }
    }
}

// ---------------- point kernel: 512 threads, warp tile 32x64, K chunks of 128 (6 stages) ----------------
#define MROWS 128
#define NPTS  32
#define XP    264                 // fp16 pitch for X rows
#define WP3   136                 // fp16 pitch for 128-k weight chunk rows (272B)
#define WSTG3 (256*WP3)           // fp16 elems per stage
__global__ __launch_bounds__(512) void point_mma_kernel(
        const float* __restrict__ pc,
        const float* __restrict__ phase_w,
        const float* __restrict__ b0, const float* __restrict__ b1,
        const float* __restrict__ b2,
        const float* __restrict__ w3, const float* __restrict__ b3,
        const float* __restrict__ coarse,
        float* __restrict__ out) {
    extern __shared__ __align__(16) __half smh[];
    __half* Xh = smh;                          // 128*264
    __half* Wt = Xh + MROWS*XP;                // 2 stages * WSTG3
    float* misc  = (float*)(Wt + 2*WSTG3);
    float* ph     = misc;                  // 256
    float* s_rel0 = ph + 256;              // 128
    float* s_rel1 = s_rel0 + 128;          // 128
    float* s_area = s_rel1 + 128;          // 128
    int*   s_pix  = (int*)(s_area + 128);  // 128
    int*   s_phof = s_pix + 128;           // 128
    float* w3s    = (float*)(s_phof + 128);// 514
    float* s_pr   = w3s + 514;             // 256

    const int t = threadIdx.x, warp = t>>5, lane = t&31;
    const int g0 = blockIdx.x * NPTS;
    const int m0 = (warp>>2)*32, n0 = (warp&3)*64;
    const int rsel = lane & 15, kgrp = (lane >> 4)*8;

    if (t < 128) {
        float p0 = phase_w[2*t], p1 = phase_w[2*t+1];
        ph[t]       = fmaf(8.f,   p0, 8.f*p1);
        ph[128 + t] = fmaf(128.f, p0, 128.f*p1);
    }
    for (int i = t; i < 514; i += 512)
        w3s[i] = (i < 512) ? w3[i] : b3[i - 512];

    if (t < MROWS) {
        const int p_local = t >> 2, s = t & 3;
        const int g = g0 + p_local;
        const int q = g & (Q_ - 1);
        const float pc0 = pc[2*g], pc1 = pc[2*g + 1];
        const float SH_P = (float)( 1.0/128.0 + 1e-6);
        const float SH_M = (float)(-1.0/128.0 + 1e-6);
        const float LO = (float)(-1.0 + 1e-6), HI = (float)(1.0 - 1e-6);
        float cy = pc0 + ((s >= 2) ? SH_P : SH_M);
        float cx = pc1 + ((s & 1) ? SH_P : SH_M);
        cy = fminf(fmaxf(cy, LO), HI);
        cx = fminf(fmaxf(cx, LO), HI);
        int iy = (int)rintf(((cy + 1.f)*128.f - 1.f)*0.5f);
        int ix = (int)rintf(((cx + 1.f)*128.f - 1.f)*0.5f);
        iy = min(max(iy, 0), 127); ix = min(max(ix, 0), 127);
        float qcy = -0.9921875f + 0.015625f*(float)iy;
        float qcx = -0.9921875f + 0.015625f*(float)ix;
        float rel0 = (pc0 - qcy)*128.f;
        float rel1 = (pc1 - qcx)*128.f;
        s_pix[t]  = iy*W_ + ix;
        s_rel0[t] = rel0;  s_rel1[t] = rel1;
        s_area[t] = fabsf(rel0*rel1) + 1e-9f;
        s_phof[t] = (q < 2) ? 0 : 128;
    }
    __syncthreads();

    // weight prefetch: 6 chunks of k=128 (3 layers x 2)
    auto wissue = [&](int g, int stg){
        const int L = g >> 1, kc = g & 1;
        __half* dstb = Wt + stg*WSTG3;
        const __half* srcb = g_Mh + L*65536 + kc*128;
        #pragma unroll
        for (int j=0;j<8;++j){
            int cid = t + j*512;            // 0..4095
            int row = cid >> 4, ch = cid & 15;
            cp16(smem_u32(dstb + row*WP3 + ch*8), srcb + row*256 + ch*8);
        }
        cp_commit();
    };
    wissue(0, 0);

    // gather + sinusoidal features -> Xh (fp16)
    {
        #pragma unroll 1
        for (int rr = 0; rr < 8; ++rr) {
            const int r = warp*8 + rr;
            const int g = g0 + (r >> 2);
            const int bb = g >> 15;
            const float* base = g_cf + ((size_t)(bb*HW_ + s_pix[r])) * 512;
            const float rel0 = s_rel0[r], rel1 = s_rel1[r];
            const float* php = ph + s_phof[r];
            #pragma unroll
            for (int i = 0; i < 2; ++i) {
                const int kp = lane + 32*i;
                const int k0 = 2*kp;
                float4 f4 = *(const float4*)(base + 256 + 2*k0);
                float2 cc = *(const float2*)(base + k0);
                float2 cs2 = *(const float2*)(base + 128 + k0);
                float2 ph2 = *(const float2*)(php + k0);
                float qf0 = fmaf(f4.x, rel0, fmaf(f4.y, rel1, ph2.x));
                float qf1 = fmaf(f4.z, rel0, fmaf(f4.w, rel1, ph2.y));
                float sv0, cv0, sv1, cv1;
                sincospif_fast(qf0, &sv0, &cv0);
                sincospif_fast(qf1, &sv1, &cv1);
                *(uint32_t*)&Xh[r*XP + k0]       = pack_hi16(make_float2(cc.x*cv0,  cc.y*cv1));
                *(uint32_t*)&Xh[r*XP + 128 + k0] = pack_hi16(make_float2(cs2.x*sv0, cs2.y*sv1));
            }
        }
    }
    asm volatile("cp.async.wait_group 0;");
    __syncthreads();    // X visible + W(0) visible

    // 6 stages (3 layers x 2 k-chunks of 128)
    float acc[2][8][4];
    #pragma unroll 1
    for (int g = 0; g < 6; ++g){
        const int L = g >> 1, kc = g & 1, stg = g & 1;
        if (kc == 0){
            #pragma unroll
            for (int i=0;i<2;++i)
                #pragma unroll
                for (int j=0;j<8;++j)
                    #pragma unroll
                    for (int q=0;q<4;++q) acc[i][j][q] = 0.f;
        }
        if (g+1 < 6) wissue(g+1, (g+1)&1);

        const __half* WH = Wt + stg*WSTG3;
        #pragma unroll
        for (int kh = 0; kh < 8; ++kh){
            const int k16 = kc*128 + kh*16;
            uint32_t AH[2][4];
            #pragma unroll
            for (int mi=0;mi<2;++mi){
                ldsm4(AH[mi][0],AH[mi][1],AH[mi][2],AH[mi][3],
                      smem_u32(Xh + (m0+mi*16+rsel)*XP + k16 + kgrp));
            }
            #pragma unroll
            for (int nj=0;nj<4;++nj){
                uint32_t r0,r1,r2,r3;
                ldsm4(r0,r1,r2,r3, smem_u32(WH + (n0+nj*16+rsel)*WP3 + kh*16 + kgrp));
                uint32_t b0r[2] = {r0, r2}, b1r[2] = {r1, r3};
                #pragma unroll
                for (int mi=0;mi<2;++mi){
                    mma16816h(acc[mi][2*nj],   AH[mi], b0r);
                    mma16816h(acc[mi][2*nj+1], AH[mi], b1r);
                }
            }
        }

        if (kc == 1){
            __syncthreads();   // all X reads of this layer done before overwrite
            const float* bg = (L==0) ? b0 : (L==1) ? b1 : b2;
            #pragma unroll
            for (int mi=0;mi<2;++mi){
                const int r = m0 + mi*16 + (lane>>2);
                #pragma unroll
                for (int ni=0;ni<8;++ni){
                    const int c = n0 + ni*8 + (lane&3)*2;
                    float2 bb = *(const float2*)&bg[c];
                    *(uint32_t*)&Xh[r*XP + c] =
                        pack_hi16(make_float2(fmaxf(acc[mi][ni][0]+bb.x, 0.f),
                                              fmaxf(acc[mi][ni][1]+bb.y, 0.f)));
                    *(uint32_t*)&Xh[(r+8)*XP + c] =
                        pack_hi16(make_float2(fmaxf(acc[mi][ni][2]+bb.x, 0.f),
                                              fmaxf(acc[mi][ni][3]+bb.y, 0.f)));
                }
            }
        }
        asm volatile("cp.async.wait_group 0;");
        __syncthreads();
    }

    // final 256->2 layer (fp32 accum from fp16 activations)
    if (t < 2*MROWS) {
        const int r = t >> 1, c = t & 1;
        const __half* rh = Xh + r*XP;
        float sum = w3s[512 + c];
        #pragma unroll 4
        for (int i = 0; i < 128; ++i) {
            uint32_t hu = *(const uint32_t*)&rh[2*i];
            __half2 hb = *reinterpret_cast<__half2*>(&hu);
            sum = fmaf(__half2float(hb.x), w3s[4*i + c], sum);
            sum = fmaf(__half2float(hb.y), w3s[4*i + 2 + c], sum);
        }
        s_pr[2*r + c] = sum;
    }
    __syncthreads();

    // local-ensemble combine + coarse residual
    if (t < 2*NPTS) {
        const int p = t >> 1, c = t & 1;
        const int rb = p*4;
        float a0 = s_area[rb+0], a1 = s_area[rb+1], a2 = s_area[rb+2], a3 = s_area[rb+3];
        float tot = a0 + a1 + a2 + a3;
        float v = s_pr[2*(rb+0)+c]*a3 + s_pr[2*(rb+1)+c]*a2
                + s_pr[2*(rb+2)+c]*a1 + s_pr[2*(rb+3)+c]*a0;
        v /= tot;
        const int g = g0 + p;
        const int bb = g >> 15, q = g & (Q_ - 1);
        const int oidx = (bb*2 + c)*Q_ + q;
        out[oidx] = v + coarse[oidx];
    }
}

// ---------------- launch ----------------
extern "C" void kernel_launch(void* const* d_in, const int* in_sizes, int n_in,
                              void* d_out, int out_size) {
    const float* feat    = (const float*)d_in[0];
    const float* pcoords = (const float*)d_in[1];
    const float* coarse  = (const float*)d_in[2];
    const float* coef_w  = (const float*)d_in[4];
    const float* coef_b  = (const float*)d_in[5];
    const float* freq_w  = (const float*)d_in[6];
    const float* freq_b  = (const float*)d_in[7];
    const float* phase_w = (const float*)d_in[8];
    const float* b0 = (const float*)d_in[10];
    const float* b1 = (const float*)d_in[12];
    const float* b2 = (const float*)d_in[14];
    const float* w3 = (const float*)d_in[15];
    const float* b3 = (const float*)d_in[16];
    float* out = (float*)d_out;

    prep_feat<<<dim3(32, 128, 2), dim3(32, 8)>>>(feat);
    border_zero<<<(B_*HP*HP + 255)/256, 256>>>();
    prep_wconv<<<(512*2304 + 255)/256, 256>>>(coef_w, coef_b, freq_w, freq_b);
    prep_wmlp<<<(3*65536 + 255)/256, 256>>>((const float*)d_in[9], (const float*)d_in[11],
                                            (const float*)d_in[13]);

    const int CSMEM = 3*ST_SZ*2;       // 122880 B
    cudaFuncSetAttribute(conv_mma_kernel, cudaFuncAttributeMaxDynamicSharedMemorySize, CSMEM);
    conv_mma_kernel<<<dim3(128, 2, 2), 256, CSMEM>>>();

    const int PSMEM = (MROWS*XP)*2 + (2*WSTG3)*2
                    + (256 + 128*3 + 514 + 256)*4 + 128*2*4 + 64;
    cudaFuncSetAttribute(point_mma_kernel, cudaFuncAttributeMaxDynamicSharedMemorySize, PSMEM);
    point_mma_kernel<<<(B_*Q_)/NPTS, 512, PSMEM>>>(pcoords, phase_w,
                                                   b0, b1, b2, w3, b3,
                                                   coarse, out);
}